// round 1
// baseline (speedup 1.0000x reference)
#include <cuda_runtime.h>
#include <cstdint>
#include <math.h>

// Problem dims (fixed for this problem instance)
#define B_DIM 8
#define S_DIM 1024
#define D_DIM 1024
#define H_DIM 4096
#define BS_DIM (B_DIM * S_DIM)            // 8192
#define SH_DIM (S_DIM * H_DIM)            // 4194304 per batch
#define KSEL   (1024u * 1024u)            // TOP_K * S = 2^20

// ---------------- scratch (device globals: allocation-free) ----------------
__device__ float g_R [(size_t)BS_DIM * H_DIM];   // relu hidden, reused for silu hidden
__device__ float g_Sc[(size_t)BS_DIM * H_DIM];   // gate scores
__device__ float g_M [B_DIM * H_DIM];            // per-column max of scores
__device__ unsigned g_hist[B_DIM * 4096];
__device__ unsigned g_prefix[B_DIM];
__device__ unsigned g_need[B_DIM];
__device__ unsigned g_keyvk[B_DIM];
__device__ unsigned char g_mask[B_DIM * H_DIM];

// monotonic float -> uint key (ascending order preserved)
__device__ __forceinline__ unsigned fkey(float f) {
    unsigned u = __float_as_uint(f);
    return u ^ ((unsigned)((int)u >> 31) | 0x80000000u);
}

// ---------------- SGEMM: C[M,N] = A[M,K] @ Bw[N,K]^T (both row-major) -------
// MODE 0: +bias, relu          (gate layer 1)
// MODE 1: +bias                (gate layer 2 / down proj)
// MODE 2: per-row mask-selected weights (up_w vs mod_w), +selected bias, silu
#define BMT 128
#define BNT 128
#define BKT 8

template <int MODE>
__global__ void __launch_bounds__(256, 2) sgemm_nt(
    const float* __restrict__ A, const float* __restrict__ Bw,
    const float* __restrict__ bias, float* __restrict__ C,
    int M, int N, int K,
    const float* __restrict__ Bw2, const float* __restrict__ bias2)
{
    __shared__ float As[BKT][BMT];
    __shared__ float Bs[BKT][BNT];

    const int tid = threadIdx.x;
    const int m0 = blockIdx.y * BMT;
    const int n0 = blockIdx.x * BNT;

    const unsigned char* mrow = nullptr;
    if (MODE == 2) mrow = g_mask + (size_t)(m0 / S_DIM) * H_DIM;

    // tile loaders: 256 threads, each loads one float4 of A and one of Bw
    const int lr = tid >> 1;            // row within tile (0..127)
    const int lc = (tid & 1) << 2;      // 0 or 4

    const float* Aptr = A + (size_t)(m0 + lr) * K + lc;
    const float* Bptr;
    {
        int h = n0 + lr;
        const float* base = Bw;
        if (MODE == 2 && mrow[h]) base = Bw2;
        Bptr = base + (size_t)h * K + lc;
    }

    const int tx = tid & 15;
    const int ty = tid >> 4;

    float acc[8][8] = {};

    for (int k0 = 0; k0 < K; k0 += BKT) {
        float4 av = *(const float4*)(Aptr + k0);
        float4 bv = *(const float4*)(Bptr + k0);
        __syncthreads();
        As[lc + 0][lr] = av.x; As[lc + 1][lr] = av.y;
        As[lc + 2][lr] = av.z; As[lc + 3][lr] = av.w;
        Bs[lc + 0][lr] = bv.x; Bs[lc + 1][lr] = bv.y;
        Bs[lc + 2][lr] = bv.z; Bs[lc + 3][lr] = bv.w;
        __syncthreads();

        #pragma unroll
        for (int kk = 0; kk < BKT; kk++) {
            float4 a0 = *(const float4*)&As[kk][ty * 8];
            float4 a1 = *(const float4*)&As[kk][ty * 8 + 4];
            float4 b0 = *(const float4*)&Bs[kk][tx * 8];
            float4 b1 = *(const float4*)&Bs[kk][tx * 8 + 4];
            float ar[8] = {a0.x, a0.y, a0.z, a0.w, a1.x, a1.y, a1.z, a1.w};
            float br[8] = {b0.x, b0.y, b0.z, b0.w, b1.x, b1.y, b1.z, b1.w};
            #pragma unroll
            for (int i = 0; i < 8; i++)
                #pragma unroll
                for (int j = 0; j < 8; j++)
                    acc[i][j] = fmaf(ar[i], br[j], acc[i][j]);
        }
    }

    #pragma unroll
    for (int i = 0; i < 8; i++) {
        int m = m0 + ty * 8 + i;
        float* crow = C + (size_t)m * N;
        #pragma unroll
        for (int j = 0; j < 8; j++) {
            int n = n0 + tx * 8 + j;
            float v = acc[i][j];
            if (MODE == 0)      { v += bias[n]; v = fmaxf(v, 0.f); }
            else if (MODE == 1) { v += bias[n]; }
            else {
                float bb = mrow[n] ? bias2[n] : bias[n];
                v += bb;
                v = v / (1.f + expf(-v));       // silu
            }
            crow[n] = v;
        }
    }
}

// ---------------- per-column max over s ------------------------------------
__global__ void colmax_kernel() {
    int b = blockIdx.y;
    int h = blockIdx.x * blockDim.x + threadIdx.x;
    const float* p = g_Sc + (size_t)b * SH_DIM + h;
    float m0 = -INFINITY, m1 = -INFINITY, m2 = -INFINITY, m3 = -INFINITY;
    #pragma unroll 4
    for (int s = 0; s < S_DIM; s += 4) {
        m0 = fmaxf(m0, p[(size_t)(s + 0) * H_DIM]);
        m1 = fmaxf(m1, p[(size_t)(s + 1) * H_DIM]);
        m2 = fmaxf(m2, p[(size_t)(s + 2) * H_DIM]);
        m3 = fmaxf(m3, p[(size_t)(s + 3) * H_DIM]);
    }
    g_M[b * H_DIM + h] = fmaxf(fmaxf(m0, m1), fmaxf(m2, m3));
}

// ---------------- exact radix-select of the k-th largest score -------------
__global__ void init_sel() {
    int i = blockIdx.x * blockDim.x + threadIdx.x;
    if (i < B_DIM * 4096) g_hist[i] = 0;
    if (i < B_DIM) { g_prefix[i] = 0; g_need[i] = KSEL; }
}

__global__ void hist_pass(unsigned prefmask, int shift, unsigned binmask) {
    int b = blockIdx.y;
    __shared__ unsigned sh[4096];
    for (int i = threadIdx.x; i < 4096; i += blockDim.x) sh[i] = 0;
    __syncthreads();

    unsigned pref = g_prefix[b] & prefmask;
    const float* p = g_Sc + (size_t)b * SH_DIM;
    int stride = gridDim.x * blockDim.x;
    for (int i = blockIdx.x * blockDim.x + threadIdx.x; i < SH_DIM; i += stride) {
        unsigned key = fkey(p[i]);
        if ((key & prefmask) == pref) {
            unsigned bin = (key >> shift) & binmask;
            unsigned am = __activemask();
            unsigned mset = __match_any_sync(am, bin);
            int leader = __ffs(mset) - 1;
            if ((threadIdx.x & 31) == leader)
                atomicAdd(&sh[bin], (unsigned)__popc(mset));
        }
    }
    __syncthreads();
    for (int i = threadIdx.x; i < 4096; i += blockDim.x)
        if (sh[i]) atomicAdd(&g_hist[b * 4096 + i], sh[i]);
}

__global__ void find_bin(int shift, int final) {
    int b = blockIdx.x;
    __shared__ unsigned sh[4096];
    for (int i = threadIdx.x; i < 4096; i += blockDim.x) {
        sh[i] = g_hist[b * 4096 + i];
        g_hist[b * 4096 + i] = 0;       // reset for next level
    }
    __syncthreads();
    if (threadIdx.x == 0) {
        unsigned nd = g_need[b];
        unsigned cum = 0;
        int bin = 4095;
        for (; bin >= 0; --bin) {
            unsigned c = sh[bin];
            if (cum + c >= nd) break;
            cum += c;
        }
        g_need[b] = nd - cum;
        g_prefix[b] |= ((unsigned)bin) << shift;
        if (final) g_keyvk[b] = g_prefix[b];
    }
}

__global__ void mask_kernel() {
    int i = blockIdx.x * blockDim.x + threadIdx.x;
    int b = i / H_DIM;
    g_mask[i] = (fkey(g_M[i]) >= g_keyvk[b]) ? 1 : 0;
}

// ---------------- launch ----------------------------------------------------
extern "C" void kernel_launch(void* const* d_in, const int* in_sizes, int n_in,
                              void* d_out, int out_size)
{
    const float* inputs = (const float*)d_in[0];
    const float* up_w   = (const float*)d_in[1];
    const float* up_b   = (const float*)d_in[2];
    const float* g1w    = (const float*)d_in[3];
    const float* g1b    = (const float*)d_in[4];
    const float* g2w    = (const float*)d_in[5];
    const float* g2b    = (const float*)d_in[6];
    const float* modw   = (const float*)d_in[7];
    const float* modb   = (const float*)d_in[8];
    const float* dww    = (const float*)d_in[9];
    const float* dwb    = (const float*)d_in[10];
    float* out = (float*)d_out;

    float* R_ptr = nullptr;
    float* Sc_ptr = nullptr;
    cudaGetSymbolAddress((void**)&R_ptr,  g_R);
    cudaGetSymbolAddress((void**)&Sc_ptr, g_Sc);

    dim3 gH(H_DIM / BNT, BS_DIM / BMT);     // 32 x 64
    dim3 gD(D_DIM / BNT, BS_DIM / BMT);     // 8 x 64

    // gate layer 1: R = relu(X @ g1^T + b1)
    sgemm_nt<0><<<gH, 256>>>(inputs, g1w, g1b, R_ptr,
                             BS_DIM, H_DIM, D_DIM, nullptr, nullptr);
    // gate layer 2: Sc = R @ g2^T + b2
    sgemm_nt<1><<<gH, 256>>>(R_ptr, g2w, g2b, Sc_ptr,
                             BS_DIM, H_DIM, H_DIM, nullptr, nullptr);

    // per-column max
    colmax_kernel<<<dim3(H_DIM / 256, B_DIM), 256>>>();

    // exact k-th-largest via 3-level radix select on monotonic keys
    init_sel<<<(B_DIM * 4096) / 256, 256>>>();
    hist_pass<<<dim3(256, B_DIM), 256>>>(0x00000000u, 20, 0xFFFu);
    find_bin<<<B_DIM, 256>>>(20, 0);
    hist_pass<<<dim3(256, B_DIM), 256>>>(0xFFF00000u, 8, 0xFFFu);
    find_bin<<<B_DIM, 256>>>(8, 0);
    hist_pass<<<dim3(256, B_DIM), 256>>>(0xFFFFFF00u, 0, 0xFFu);
    find_bin<<<B_DIM, 256>>>(0, 1);

    mask_kernel<<<(B_DIM * H_DIM) / 256, 256>>>();

    // modulated up-projection with per-row weight select, fused silu.
    // Each 128-row M-tile is within one batch (S % 128 == 0), so the B-tile
    // loader picks mod_w[h] vs up_w[h] by g_mask — no extra FLOPs.
    sgemm_nt<2><<<gH, 256>>>(inputs, up_w, up_b, R_ptr,
                             BS_DIM, H_DIM, D_DIM, modw, modb);

    // down projection: out = Hact @ down_w^T + down_b
    sgemm_nt<1><<<gD, 256>>>(R_ptr, dww, dwb, out,
                             BS_DIM, D_DIM, H_DIM, nullptr, nullptr);
}

// round 3
// speedup vs baseline: 3.6600x; 3.6600x over previous
#include <cuda_runtime.h>
#include <cstdint>
#include <math.h>

// Problem dims (fixed)
#define B_DIM 8
#define S_DIM 1024
#define D_DIM 1024
#define H_DIM 4096
#define BS_DIM (B_DIM * S_DIM)            // 8192
#define SH_DIM (S_DIM * H_DIM)            // 4194304 per batch
#define KSEL   (1024u * 1024u)            // TOP_K * S = 2^20

// ---------------- scratch (device globals) ---------------------------------
__device__ __align__(1024) float g_R [(size_t)BS_DIM * H_DIM];   // R / H
__device__ __align__(1024) float g_Sc[(size_t)BS_DIM * H_DIM];   // scores
__device__ __align__(1024) float g_X [(size_t)BS_DIM * D_DIM];   // rounded inputs
__device__ __align__(1024) float g_W1[(size_t)H_DIM * D_DIM];
__device__ __align__(1024) float g_W2[(size_t)H_DIM * H_DIM];
__device__ __align__(1024) float g_Wd[(size_t)D_DIM * H_DIM];
__device__ __align__(1024) float g_Wu[(size_t)B_DIM * H_DIM * D_DIM]; // merged
__device__ float g_Bu[B_DIM * H_DIM];
__device__ float g_M [B_DIM * H_DIM];
__device__ unsigned g_hist[B_DIM * 4096];
__device__ unsigned g_prefix[B_DIM];
__device__ unsigned g_need[B_DIM];
__device__ unsigned g_keyvk[B_DIM];
__device__ unsigned char g_mask[B_DIM * H_DIM];

// ---------------- helpers ---------------------------------------------------
__device__ __forceinline__ unsigned fkey(float f) {
    unsigned u = __float_as_uint(f);
    return u ^ ((unsigned)((int)u >> 31) | 0x80000000u);
}
__device__ __forceinline__ float rtf32(float x) {   // round-to-nearest tf32
    uint32_t r;
    asm("cvt.rna.tf32.f32 %0, %1;" : "=r"(r) : "f"(x));
    return __uint_as_float(r);
}
__device__ __forceinline__ uint32_t smem_u32(const void* p) {
    uint32_t a;
    asm("{ .reg .u64 t; cvta.to.shared.u64 t, %1; cvt.u32.u64 %0, t; }"
        : "=r"(a) : "l"(p));
    return a;
}
__device__ __forceinline__ void cp16(uint32_t dst, const void* src) {
    asm volatile("cp.async.cg.shared.global [%0], [%1], 16;"
                 :: "r"(dst), "l"(src));
}
#define CP_COMMIT() asm volatile("cp.async.commit_group;" ::: "memory")
#define CP_WAIT2()  asm volatile("cp.async.wait_group 2;" ::: "memory")
#define CP_WAIT0()  asm volatile("cp.async.wait_group 0;" ::: "memory")

__device__ __forceinline__ void mma_tf32(float* c, const uint32_t* a,
                                         const uint32_t* b) {
    asm volatile(
        "mma.sync.aligned.m16n8k8.row.col.f32.tf32.tf32.f32 "
        "{%0,%1,%2,%3}, {%4,%5,%6,%7}, {%8,%9}, {%0,%1,%2,%3};"
        : "+f"(c[0]), "+f"(c[1]), "+f"(c[2]), "+f"(c[3])
        : "r"(a[0]), "r"(a[1]), "r"(a[2]), "r"(a[3]), "r"(b[0]), "r"(b[1]));
}

// ---------------- tf32 mma.sync GEMM: C[M,N] = A[M,K] @ Bw[rows,K]^T --------
// tile 128x128, BK=32 floats, 3-stage cp.async, 256 thr (8 warps, 32x64 each)
// MODE 0: +bias, relu, rtf32     MODE 1: +bias     MODE 2: merged W, silu, rtf32
#define STG_A 16384
#define STG   32768
#define NSTG  3
#define GEMM_SMEM (NSTG * STG)

template <int MODE>
__global__ void __launch_bounds__(256, 2) gemm_mma(
    const float* __restrict__ A, const float* __restrict__ Bw,
    const float* __restrict__ bias, float* __restrict__ C,
    int K, int ldc)
{
    extern __shared__ char smraw[];
    const int tid = threadIdx.x;
    const int m0 = blockIdx.x * 128;
    const int n0 = blockIdx.y * 128;
    const int batch = m0 >> 10;
    const int brow = n0 + (MODE == 2 ? batch * H_DIM : 0);
    const int boff = (MODE == 2) ? batch * H_DIM : 0;
    const uint32_t sbase = smem_u32(smraw);

    // ---- cp.async geometry: thread -> (row = tid/8 + 32*jj, chunk = tid%8)
    const int lrow = tid >> 3;
    const int lc   = tid & 7;
    const uint32_t dstoff = (uint32_t)lrow * 128u
                          + (uint32_t)((lc ^ (lrow & 7)) * 16);
    const char* srcA = (const char*)(A  + (size_t)(m0  + lrow) * K) + lc * 16;
    const char* srcB = (const char*)(Bw + (size_t)(brow + lrow) * K) + lc * 16;
    const size_t rowstep = (size_t)K * 128;   // 32 rows * K floats * 4B

    const int NK = K >> 5;

    auto issue = [&](int t) {
        uint32_t sa = sbase + (uint32_t)(t % NSTG) * STG;
        const char* pa = srcA + (size_t)t * 128;
        const char* pb = srcB + (size_t)t * 128;
        #pragma unroll
        for (int jj = 0; jj < 4; jj++)
            cp16(sa + jj * 4096 + dstoff, pa + jj * rowstep);
        #pragma unroll
        for (int jj = 0; jj < 4; jj++)
            cp16(sa + STG_A + jj * 4096 + dstoff, pb + jj * rowstep);
        CP_COMMIT();
    };

    // ---- compute geometry
    const int w   = tid >> 5;
    const int q   = (tid >> 2) & 7;     // lane/4
    const int p   = tid & 3;            // lane%4
    const int wm0 = (w & 3) * 32;
    const int wn0 = (w >> 2) * 64;
    const uint32_t key = (uint32_t)q * 16u;
    const uint32_t rowA = (uint32_t)(wm0 + q) * 128u;
    const uint32_t rowB = (uint32_t)(wn0 + q) * 128u + STG_A;

    float acc[2][8][4];
    #pragma unroll
    for (int i = 0; i < 2; i++)
        #pragma unroll
        for (int j = 0; j < 8; j++)
            #pragma unroll
            for (int r = 0; r < 4; r++) acc[i][j][r] = 0.f;

    issue(0); issue(1);

    for (int kc = 0; kc < NK; kc++) {
        if (kc + 2 < NK) { issue(kc + 2); CP_WAIT2(); }
        else             { CP_WAIT0(); }
        __syncthreads();

        const char* st = smraw + (kc % NSTG) * STG;
        #pragma unroll
        for (int ks = 0; ks < 4; ks++) {
            uint32_t o0 = ((uint32_t)(ks * 32 + p * 4)) ^ key;
            uint32_t o1 = ((uint32_t)(ks * 32 + 16 + p * 4)) ^ key;
            uint32_t a[2][4], b[8][2];
            #pragma unroll
            for (int i = 0; i < 2; i++) {
                const char* ba = st + rowA + i * 2048;
                a[i][0] = *(const uint32_t*)(ba + o0);
                a[i][1] = *(const uint32_t*)(ba + 1024 + o0);
                a[i][2] = *(const uint32_t*)(ba + o1);
                a[i][3] = *(const uint32_t*)(ba + 1024 + o1);
            }
            #pragma unroll
            for (int j = 0; j < 8; j++) {
                const char* bb = st + rowB + j * 1024;
                b[j][0] = *(const uint32_t*)(bb + o0);
                b[j][1] = *(const uint32_t*)(bb + o1);
            }
            #pragma unroll
            for (int i = 0; i < 2; i++)
                #pragma unroll
                for (int j = 0; j < 8; j++)
                    mma_tf32(acc[i][j], a[i], b[j]);
        }
        __syncthreads();
    }

    // ---- epilogue: bias + activation, direct float2 stores
    #pragma unroll
    for (int i = 0; i < 2; i++) {
        int mr = m0 + wm0 + i * 16 + q;
        #pragma unroll
        for (int j = 0; j < 8; j++) {
            int nc = n0 + wn0 + j * 8 + p * 2;
            float2 bb = *(const float2*)(bias + boff + nc);
            float v0 = acc[i][j][0] + bb.x;
            float v1 = acc[i][j][1] + bb.y;
            float v2 = acc[i][j][2] + bb.x;
            float v3 = acc[i][j][3] + bb.y;
            if (MODE == 0) {
                v0 = rtf32(fmaxf(v0, 0.f)); v1 = rtf32(fmaxf(v1, 0.f));
                v2 = rtf32(fmaxf(v2, 0.f)); v3 = rtf32(fmaxf(v3, 0.f));
            } else if (MODE == 2) {
                v0 = rtf32(v0 / (1.f + expf(-v0)));
                v1 = rtf32(v1 / (1.f + expf(-v1)));
                v2 = rtf32(v2 / (1.f + expf(-v2)));
                v3 = rtf32(v3 / (1.f + expf(-v3)));
            }
            float2 r0 = make_float2(v0, v1), r1 = make_float2(v2, v3);
            *(float2*)(C + (size_t)mr * ldc + nc) = r0;
            *(float2*)(C + (size_t)(mr + 8) * ldc + nc) = r1;
        }
    }
}

// ---------------- aux kernels ----------------------------------------------
__global__ void round_copy(const float* __restrict__ src, float* __restrict__ dst,
                           int n4) {
    int i = blockIdx.x * blockDim.x + threadIdx.x;
    if (i < n4) {
        float4 v = ((const float4*)src)[i];
        v.x = rtf32(v.x); v.y = rtf32(v.y); v.z = rtf32(v.z); v.w = rtf32(v.w);
        ((float4*)dst)[i] = v;
    }
}

__global__ void merge_kernel(const float* __restrict__ upw, const float* __restrict__ modw,
                             const float* __restrict__ upb, const float* __restrict__ modb) {
    int row = blockIdx.x;                   // b*H + h
    int h = row & (H_DIM - 1);
    bool m = g_mask[row] != 0;
    const float4* src = (const float4*)((m ? modw : upw) + (size_t)h * D_DIM);
    float4* dst = (float4*)(g_Wu + (size_t)row * D_DIM);
    int i = threadIdx.x;                    // 256 threads, D/4 = 256 float4s
    float4 v = src[i];
    v.x = rtf32(v.x); v.y = rtf32(v.y); v.z = rtf32(v.z); v.w = rtf32(v.w);
    dst[i] = v;
    if (i == 0) g_Bu[row] = m ? modb[h] : upb[h];
}

__global__ void colmax_kernel() {
    int b = blockIdx.y;
    int h = blockIdx.x * blockDim.x + threadIdx.x;
    const float* p = g_Sc + (size_t)b * SH_DIM + h;
    float m0 = -INFINITY, m1 = -INFINITY, m2 = -INFINITY, m3 = -INFINITY;
    #pragma unroll 4
    for (int s = 0; s < S_DIM; s += 4) {
        m0 = fmaxf(m0, p[(size_t)(s + 0) * H_DIM]);
        m1 = fmaxf(m1, p[(size_t)(s + 1) * H_DIM]);
        m2 = fmaxf(m2, p[(size_t)(s + 2) * H_DIM]);
        m3 = fmaxf(m3, p[(size_t)(s + 3) * H_DIM]);
    }
    g_M[b * H_DIM + h] = fmaxf(fmaxf(m0, m1), fmaxf(m2, m3));
}

__global__ void init_sel() {
    int i = blockIdx.x * blockDim.x + threadIdx.x;
    if (i < B_DIM * 4096) g_hist[i] = 0;
    if (i < B_DIM) { g_prefix[i] = 0; g_need[i] = KSEL; }
}

__global__ void hist_pass(unsigned prefmask, int shift, unsigned binmask) {
    int b = blockIdx.y;
    __shared__ unsigned sh[4096];
    for (int i = threadIdx.x; i < 4096; i += blockDim.x) sh[i] = 0;
    __syncthreads();
    unsigned pref = g_prefix[b] & prefmask;
    const float* p = g_Sc + (size_t)b * SH_DIM;
    int stride = gridDim.x * blockDim.x;
    for (int i = blockIdx.x * blockDim.x + threadIdx.x; i < SH_DIM; i += stride) {
        unsigned key = fkey(p[i]);
        if ((key & prefmask) == pref) {
            unsigned bin = (key >> shift) & binmask;
            unsigned am = __activemask();
            unsigned mset = __match_any_sync(am, bin);
            int leader = __ffs(mset) - 1;
            if ((threadIdx.x & 31) == leader)
                atomicAdd(&sh[bin], (unsigned)__popc(mset));
        }
    }
    __syncthreads();
    for (int i = threadIdx.x; i < 4096; i += blockDim.x)
        if (sh[i]) atomicAdd(&g_hist[b * 4096 + i], sh[i]);
}

__global__ void find_bin(int shift, int final) {
    int b = blockIdx.x;
    __shared__ unsigned sh[4096];
    for (int i = threadIdx.x; i < 4096; i += blockDim.x) {
        sh[i] = g_hist[b * 4096 + i];
        g_hist[b * 4096 + i] = 0;
    }
    __syncthreads();
    if (threadIdx.x == 0) {
        unsigned nd = g_need[b], cum = 0;
        int bin = 4095;
        for (; bin >= 0; --bin) {
            unsigned c = sh[bin];
            if (cum + c >= nd) break;
            cum += c;
        }
        g_need[b] = nd - cum;
        g_prefix[b] |= ((unsigned)bin) << shift;
        if (final) g_keyvk[b] = g_prefix[b];
    }
}

__global__ void mask_kernel() {
    int i = blockIdx.x * blockDim.x + threadIdx.x;
    int b = i / H_DIM;
    g_mask[i] = (fkey(g_M[i]) >= g_keyvk[b]) ? 1 : 0;
}

// ---------------- launch ----------------------------------------------------
extern "C" void kernel_launch(void* const* d_in, const int* in_sizes, int n_in,
                              void* d_out, int out_size)
{
    const float* inputs = (const float*)d_in[0];
    const float* up_w   = (const float*)d_in[1];
    const float* up_b   = (const float*)d_in[2];
    const float* g1w    = (const float*)d_in[3];
    const float* g1b    = (const float*)d_in[4];
    const float* g2w    = (const float*)d_in[5];
    const float* g2b    = (const float*)d_in[6];
    const float* modw   = (const float*)d_in[7];
    const float* modb   = (const float*)d_in[8];
    const float* dww    = (const float*)d_in[9];
    const float* dwb    = (const float*)d_in[10];
    float* out = (float*)d_out;

    float *R, *Sc, *X, *W1, *W2, *Wd, *Wu, *Bu;
    cudaGetSymbolAddress((void**)&R,  g_R);
    cudaGetSymbolAddress((void**)&Sc, g_Sc);
    cudaGetSymbolAddress((void**)&X,  g_X);
    cudaGetSymbolAddress((void**)&W1, g_W1);
    cudaGetSymbolAddress((void**)&W2, g_W2);
    cudaGetSymbolAddress((void**)&Wd, g_Wd);
    cudaGetSymbolAddress((void**)&Wu, g_Wu);
    cudaGetSymbolAddress((void**)&Bu, g_Bu);

    cudaFuncSetAttribute(gemm_mma<0>, cudaFuncAttributeMaxDynamicSharedMemorySize, GEMM_SMEM);
    cudaFuncSetAttribute(gemm_mma<1>, cudaFuncAttributeMaxDynamicSharedMemorySize, GEMM_SMEM);
    cudaFuncSetAttribute(gemm_mma<2>, cudaFuncAttributeMaxDynamicSharedMemorySize, GEMM_SMEM);

    // pre-round all GEMM operands to tf32 (RNA, unbiased)
    round_copy<<<(BS_DIM * D_DIM / 4 + 255) / 256, 256>>>(inputs, X, BS_DIM * D_DIM / 4);
    round_copy<<<(H_DIM * D_DIM / 4 + 255) / 256, 256>>>(g1w, W1, H_DIM * D_DIM / 4);
    round_copy<<<(H_DIM * H_DIM / 4 + 255) / 256, 256>>>(g2w, W2, H_DIM * H_DIM / 4);
    round_copy<<<(D_DIM * H_DIM / 4 + 255) / 256, 256>>>(dww, Wd, D_DIM * H_DIM / 4);

    dim3 gH(BS_DIM / 128, H_DIM / 128);     // 64 x 32
    dim3 gD(BS_DIM / 128, D_DIM / 128);     // 64 x 8

    // gate L1: R = rtf32(relu(X @ W1^T + b1))
    gemm_mma<0><<<gH, 256, GEMM_SMEM>>>(X, W1, g1b, R, D_DIM, H_DIM);
    // gate L2: Sc = R @ W2^T + b2
    gemm_mma<1><<<gH, 256, GEMM_SMEM>>>(R, W2, g2b, Sc, H_DIM, H_DIM);

    // selection (exact; mask margin >> tf32 noise)
    colmax_kernel<<<dim3(H_DIM / 256, B_DIM), 256>>>();
    init_sel<<<(B_DIM * 4096) / 256, 256>>>();
    hist_pass<<<dim3(256, B_DIM), 256>>>(0x00000000u, 20, 0xFFFu);
    find_bin<<<B_DIM, 256>>>(20, 0);
    hist_pass<<<dim3(256, B_DIM), 256>>>(0xFFF00000u, 8, 0xFFFu);
    find_bin<<<B_DIM, 256>>>(8, 0);
    hist_pass<<<dim3(256, B_DIM), 256>>>(0xFFFFFF00u, 0, 0xFFu);
    find_bin<<<B_DIM, 256>>>(0, 1);
    mask_kernel<<<(B_DIM * H_DIM) / 256, 256>>>();

    // merged per-batch up/mod weights + bias (rounded)
    merge_kernel<<<B_DIM * H_DIM, 256>>>(up_w, modw, up_b, modb);

    // H = rtf32(silu(X @ Wu^T + Bu))  (per-batch weights)
    gemm_mma<2><<<gH, 256, GEMM_SMEM>>>(X, Wu, Bu, R, D_DIM, H_DIM);
    // out = H @ Wd^T + down_b
    gemm_mma<1><<<gD, 256, GEMM_SMEM>>>(R, Wd, dwb, out, H_DIM, D_DIM);
}

// round 9
// speedup vs baseline: 6.0995x; 1.6666x over previous
#include <cuda_runtime.h>
#include <cuda_fp16.h>
#include <cstdint>
#include <math.h>

// Problem dims (fixed)
#define B_DIM 8
#define S_DIM 1024
#define D_DIM 1024
#define H_DIM 4096
#define BS_DIM (B_DIM * S_DIM)            // 8192
#define SH_DIM (S_DIM * H_DIM)            // 4194304 per batch
#define KSEL   (1024u * 1024u)            // TOP_K * S = 2^20

// ---------------- scratch (device globals) ---------------------------------
__device__ __align__(1024) __half g_Xh[(size_t)BS_DIM * D_DIM];
__device__ __align__(1024) __half g_W1[(size_t)H_DIM * D_DIM];
__device__ __align__(1024) __half g_W2[(size_t)H_DIM * H_DIM];
__device__ __align__(1024) __half g_Wd[(size_t)D_DIM * H_DIM];
__device__ __align__(1024) __half g_Wu[(size_t)B_DIM * H_DIM * D_DIM]; // merged
__device__ __align__(1024) __half g_Rh[(size_t)BS_DIM * H_DIM];  // relu R / silu H
__device__ __align__(1024) float  g_Sc[(size_t)BS_DIM * H_DIM];  // scores f32
__device__ float g_Bu[B_DIM * H_DIM];
__device__ float g_M [B_DIM * H_DIM];
__device__ unsigned g_hist[B_DIM * 4096];
__device__ unsigned g_prefix[B_DIM];
__device__ unsigned g_need[B_DIM];
__device__ unsigned g_keyvk[B_DIM];
__device__ unsigned char g_mask[B_DIM * H_DIM];

// ---------------- helpers ---------------------------------------------------
__device__ __forceinline__ unsigned fkey(float f) {
    unsigned u = __float_as_uint(f);
    return u ^ ((unsigned)((int)u >> 31) | 0x80000000u);
}
__device__ __forceinline__ uint32_t smem_u32(const void* p) {
    uint32_t a;
    asm("{ .reg .u64 t; cvta.to.shared.u64 t, %1; cvt.u32.u64 %0, t; }"
        : "=r"(a) : "l"(p));
    return a;
}
__device__ __forceinline__ void cp16(uint32_t dst, const void* src) {
    asm volatile("cp.async.cg.shared.global [%0], [%1], 16;"
                 :: "r"(dst), "l"(src));
}
#define CP_COMMIT() asm volatile("cp.async.commit_group;" ::: "memory")
#define CP_WAIT2()  asm volatile("cp.async.wait_group 2;" ::: "memory")
#define CP_WAIT0()  asm volatile("cp.async.wait_group 0;" ::: "memory")

__device__ __forceinline__ void mma_f16(float* c, const uint32_t* a,
                                        const uint32_t* b) {
    asm volatile(
        "mma.sync.aligned.m16n8k16.row.col.f32.f16.f16.f32 "
        "{%0,%1,%2,%3}, {%4,%5,%6,%7}, {%8,%9}, {%0,%1,%2,%3};"
        : "+f"(c[0]), "+f"(c[1]), "+f"(c[2]), "+f"(c[3])
        : "r"(a[0]), "r"(a[1]), "r"(a[2]), "r"(a[3]), "r"(b[0]), "r"(b[1]));
}

// ---------------- fp16 mma GEMM: C[M,N] = A[M,K] @ Bw[rows,K]^T -------------
// tile 128x128, BK=64 halfs (128B rows), 3-stage cp.async, 8 warps (32x64)
// MODE 0: +bias, relu,  half out      (gate L1 -> R)
// MODE 1: +bias,        float out     (gate L2 scores / down proj)
// MODE 2: merged per-batch W/bias, silu, half out
#define STG_A 16384
#define STG   32768
#define NSTG  3
#define GEMM_SMEM (NSTG * STG)

template <int MODE>
__global__ void __launch_bounds__(256, 2) gemm_h(
    const __half* __restrict__ A, const __half* __restrict__ Bw,
    const float* __restrict__ bias, void* __restrict__ Cv,
    int K, int ldc)
{
    extern __shared__ char smraw[];
    const int tid = threadIdx.x;
    const int m0 = blockIdx.x * 128;
    const int n0 = blockIdx.y * 128;
    const int batch = m0 >> 10;
    const int brow = n0 + (MODE == 2 ? batch * H_DIM : 0);
    const int boff = (MODE == 2) ? batch * H_DIM : 0;
    const uint32_t sbase = smem_u32(smraw);

    // cp.async geometry: thread -> (row = tid/8 + 32*jj, 16B chunk = tid%8)
    const int lrow = tid >> 3;
    const int lc   = tid & 7;
    const uint32_t dstoff = (uint32_t)lrow * 128u
                          + (uint32_t)((lc ^ (lrow & 7)) * 16);
    const char* srcA = (const char*)(A  + (size_t)(m0  + lrow) * K) + lc * 16;
    const char* srcB = (const char*)(Bw + (size_t)(brow + lrow) * K) + lc * 16;
    const size_t rowstep = (size_t)K * 64;     // 32 rows * K halfs * 2B

    const int NK = K >> 6;                     // BK = 64 halfs

    auto issue = [&](int t) {
        uint32_t sa = sbase + (uint32_t)(t % NSTG) * STG;
        const char* pa = srcA + (size_t)t * 128;
        const char* pb = srcB + (size_t)t * 128;
        #pragma unroll
        for (int jj = 0; jj < 4; jj++)
            cp16(sa + jj * 4096 + dstoff, pa + jj * rowstep);
        #pragma unroll
        for (int jj = 0; jj < 4; jj++)
            cp16(sa + STG_A + jj * 4096 + dstoff, pb + jj * rowstep);
        CP_COMMIT();
    };

    // compute geometry (warp 32x64 tile, 2x8 m16n8k16 frags)
    const int w   = tid >> 5;
    const int q   = (tid >> 2) & 7;     // lane/4
    const int p   = tid & 3;            // lane%4
    const int wm0 = (w & 3) * 32;
    const int wn0 = (w >> 2) * 64;
    const uint32_t key = (uint32_t)q * 16u;
    const uint32_t rowA = (uint32_t)(wm0 + q) * 128u;
    const uint32_t rowB = (uint32_t)(wn0 + q) * 128u + STG_A;

    float acc[2][8][4];
    #pragma unroll
    for (int i = 0; i < 2; i++)
        #pragma unroll
        for (int j = 0; j < 8; j++)
            #pragma unroll
            for (int r = 0; r < 4; r++) acc[i][j][r] = 0.f;

    issue(0); issue(1);

    for (int kc = 0; kc < NK; kc++) {
        if (kc + 2 < NK) { issue(kc + 2); CP_WAIT2(); }
        else             { CP_WAIT0(); }
        __syncthreads();

        const char* st = smraw + (kc % NSTG) * STG;
        #pragma unroll
        for (int ks = 0; ks < 4; ks++) {       // 4 x k16 per 64-half chunk
            uint32_t o0 = ((uint32_t)(ks * 32 + p * 4)) ^ key;
            uint32_t o1 = ((uint32_t)(ks * 32 + 16 + p * 4)) ^ key;
            uint32_t a[2][4], b[8][2];
            #pragma unroll
            for (int i = 0; i < 2; i++) {
                const char* ba = st + rowA + i * 2048;
                a[i][0] = *(const uint32_t*)(ba + o0);
                a[i][1] = *(const uint32_t*)(ba + 1024 + o0);
                a[i][2] = *(const uint32_t*)(ba + o1);
                a[i][3] = *(const uint32_t*)(ba + 1024 + o1);
            }
            #pragma unroll
            for (int j = 0; j < 8; j++) {
                const char* bb = st + rowB + j * 1024;
                b[j][0] = *(const uint32_t*)(bb + o0);
                b[j][1] = *(const uint32_t*)(bb + o1);
            }
            #pragma unroll
            for (int i = 0; i < 2; i++)
                #pragma unroll
                for (int j = 0; j < 8; j++)
                    mma_f16(acc[i][j], a[i], b[j]);
        }
        __syncthreads();
    }

    // epilogue: bias + activation
    #pragma unroll
    for (int i = 0; i < 2; i++) {
        int mr = m0 + wm0 + i * 16 + q;
        #pragma unroll
        for (int j = 0; j < 8; j++) {
            int nc = n0 + wn0 + j * 8 + p * 2;
            float2 bb = *(const float2*)(bias + boff + nc);
            float v0 = acc[i][j][0] + bb.x;
            float v1 = acc[i][j][1] + bb.y;
            float v2 = acc[i][j][2] + bb.x;
            float v3 = acc[i][j][3] + bb.y;
            if (MODE == 0) {
                v0 = fmaxf(v0, 0.f); v1 = fmaxf(v1, 0.f);
                v2 = fmaxf(v2, 0.f); v3 = fmaxf(v3, 0.f);
                __half* Ch = (__half*)Cv;
                *(__half2*)(Ch + (size_t)mr * ldc + nc) = __floats2half2_rn(v0, v1);
                *(__half2*)(Ch + (size_t)(mr + 8) * ldc + nc) = __floats2half2_rn(v2, v3);
            } else if (MODE == 2) {
                v0 = v0 / (1.f + expf(-v0));
                v1 = v1 / (1.f + expf(-v1));
                v2 = v2 / (1.f + expf(-v2));
                v3 = v3 / (1.f + expf(-v3));
                __half* Ch = (__half*)Cv;
                *(__half2*)(Ch + (size_t)mr * ldc + nc) = __floats2half2_rn(v0, v1);
                *(__half2*)(Ch + (size_t)(mr + 8) * ldc + nc) = __floats2half2_rn(v2, v3);
            } else {
                float* Cf = (float*)Cv;
                *(float2*)(Cf + (size_t)mr * ldc + nc) = make_float2(v0, v1);
                *(float2*)(Cf + (size_t)(mr + 8) * ldc + nc) = make_float2(v2, v3);
            }
        }
    }
}

// ---------------- aux kernels ----------------------------------------------
__global__ void h_copy(const float* __restrict__ src, __half* __restrict__ dst,
                       int n4) {
    int i = blockIdx.x * blockDim.x + threadIdx.x;
    if (i < n4) {
        float4 v = ((const float4*)src)[i];
        __half2* d2 = (__half2*)(dst + (size_t)i * 4);
        d2[0] = __floats2half2_rn(v.x, v.y);
        d2[1] = __floats2half2_rn(v.z, v.w);
    }
}

__global__ void merge_kernel(const float* __restrict__ upw, const float* __restrict__ modw,
                             const float* __restrict__ upb, const float* __restrict__ modb) {
    int row = blockIdx.x;                   // b*H + h
    int h = row & (H_DIM - 1);
    bool m = g_mask[row] != 0;
    const float4* src = (const float4*)((m ? modw : upw) + (size_t)h * D_DIM);
    int i = threadIdx.x;                    // 256 threads, D/4 = 256 float4s
    float4 v = src[i];
    __half2* dst = (__half2*)(g_Wu + (size_t)row * D_DIM + (size_t)i * 4);
    dst[0] = __floats2half2_rn(v.x, v.y);
    dst[1] = __floats2half2_rn(v.z, v.w);
    if (i == 0) g_Bu[row] = m ? modb[h] : upb[h];
}

__global__ void colmax_kernel() {
    int b = blockIdx.y;
    int h = blockIdx.x * blockDim.x + threadIdx.x;
    const float* p = g_Sc + (size_t)b * SH_DIM + h;
    float m0 = -INFINITY, m1 = -INFINITY, m2 = -INFINITY, m3 = -INFINITY;
    #pragma unroll 4
    for (int s = 0; s < S_DIM; s += 4) {
        m0 = fmaxf(m0, p[(size_t)(s + 0) * H_DIM]);
        m1 = fmaxf(m1, p[(size_t)(s + 1) * H_DIM]);
        m2 = fmaxf(m2, p[(size_t)(s + 2) * H_DIM]);
        m3 = fmaxf(m3, p[(size_t)(s + 3) * H_DIM]);
    }
    g_M[b * H_DIM + h] = fmaxf(fmaxf(m0, m1), fmaxf(m2, m3));
}

__global__ void init_sel() {
    int i = blockIdx.x * blockDim.x + threadIdx.x;
    if (i < B_DIM * 4096) g_hist[i] = 0;
    if (i < B_DIM) { g_prefix[i] = 0; g_need[i] = KSEL; }
}

__global__ void hist_pass(unsigned prefmask, int shift, unsigned binmask) {
    int b = blockIdx.y;
    __shared__ unsigned sh[4096];
    for (int i = threadIdx.x; i < 4096; i += blockDim.x) sh[i] = 0;
    __syncthreads();
    unsigned pref = g_prefix[b] & prefmask;
    const float* p = g_Sc + (size_t)b * SH_DIM;
    int stride = gridDim.x * blockDim.x;
    for (int i = blockIdx.x * blockDim.x + threadIdx.x; i < SH_DIM; i += stride) {
        unsigned key = fkey(p[i]);
        if ((key & prefmask) == pref) {
            unsigned bin = (key >> shift) & binmask;
            unsigned am = __activemask();
            unsigned mset = __match_any_sync(am, bin);
            int leader = __ffs(mset) - 1;
            if ((threadIdx.x & 31) == leader)
                atomicAdd(&sh[bin], (unsigned)__popc(mset));
        }
    }
    __syncthreads();
    for (int i = threadIdx.x; i < 4096; i += blockDim.x)
        if (sh[i]) atomicAdd(&g_hist[b * 4096 + i], sh[i]);
}

__global__ void find_bin(int shift, int final) {
    int b = blockIdx.x;
    __shared__ unsigned sh[4096];
    for (int i = threadIdx.x; i < 4096; i += blockDim.x) {
        sh[i] = g_hist[b * 4096 + i];
        g_hist[b * 4096 + i] = 0;
    }
    __syncthreads();
    if (threadIdx.x == 0) {
        unsigned nd = g_need[b], cum = 0;
        int bin = 4095;
        for (; bin >= 0; --bin) {
            unsigned c = sh[bin];
            if (cum + c >= nd) break;
            cum += c;
        }
        g_need[b] = nd - cum;
        g_prefix[b] |= ((unsigned)bin) << shift;
        if (final) g_keyvk[b] = g_prefix[b];
    }
}

__global__ void mask_kernel() {
    int i = blockIdx.x * blockDim.x + threadIdx.x;
    int b = i / H_DIM;
    g_mask[i] = (fkey(g_M[i]) >= g_keyvk[b]) ? 1 : 0;
}

// ---------------- launch ----------------------------------------------------
extern "C" void kernel_launch(void* const* d_in, const int* in_sizes, int n_in,
                              void* d_out, int out_size)
{
    const float* inputs = (const float*)d_in[0];
    const float* up_w   = (const float*)d_in[1];
    const float* up_b   = (const float*)d_in[2];
    const float* g1w    = (const float*)d_in[3];
    const float* g1b    = (const float*)d_in[4];
    const float* g2w    = (const float*)d_in[5];
    const float* g2b    = (const float*)d_in[6];
    const float* modw   = (const float*)d_in[7];
    const float* modb   = (const float*)d_in[8];
    const float* dww    = (const float*)d_in[9];
    const float* dwb    = (const float*)d_in[10];
    float* out = (float*)d_out;

    __half *Xh, *W1, *W2, *Wd, *Wu, *Rh;
    float *Sc, *Bu;
    cudaGetSymbolAddress((void**)&Xh, g_Xh);
    cudaGetSymbolAddress((void**)&W1, g_W1);
    cudaGetSymbolAddress((void**)&W2, g_W2);
    cudaGetSymbolAddress((void**)&Wd, g_Wd);
    cudaGetSymbolAddress((void**)&Wu, g_Wu);
    cudaGetSymbolAddress((void**)&Rh, g_Rh);
    cudaGetSymbolAddress((void**)&Sc, g_Sc);
    cudaGetSymbolAddress((void**)&Bu, g_Bu);

    cudaFuncSetAttribute(gemm_h<0>, cudaFuncAttributeMaxDynamicSharedMemorySize, GEMM_SMEM);
    cudaFuncSetAttribute(gemm_h<1>, cudaFuncAttributeMaxDynamicSharedMemorySize, GEMM_SMEM);
    cudaFuncSetAttribute(gemm_h<2>, cudaFuncAttributeMaxDynamicSharedMemorySize, GEMM_SMEM);

    // fp16 operand conversion (RN, unbiased; same 10-bit mantissa as tf32)
    h_copy<<<(BS_DIM * D_DIM / 4 + 255) / 256, 256>>>(inputs, Xh, BS_DIM * D_DIM / 4);
    h_copy<<<(H_DIM * D_DIM / 4 + 255) / 256, 256>>>(g1w, W1, H_DIM * D_DIM / 4);
    h_copy<<<(H_DIM * H_DIM / 4 + 255) / 256, 256>>>(g2w, W2, H_DIM * H_DIM / 4);
    h_copy<<<(D_DIM * H_DIM / 4 + 255) / 256, 256>>>(dww, Wd, D_DIM * H_DIM / 4);

    dim3 gH(BS_DIM / 128, H_DIM / 128);     // 64 x 32
    dim3 gD(BS_DIM / 128, D_DIM / 128);     // 64 x 8

    // gate L1: R = relu(X @ W1^T + b1)  -> half
    gemm_h<0><<<gH, 256, GEMM_SMEM>>>(Xh, W1, g1b, Rh, D_DIM, H_DIM);
    // gate L2: Sc = R @ W2^T + b2       -> float
    gemm_h<1><<<gH, 256, GEMM_SMEM>>>(Rh, W2, g2b, Sc, H_DIM, H_DIM);

    // exact selection on the computed scores
    colmax_kernel<<<dim3(H_DIM / 256, B_DIM), 256>>>();
    init_sel<<<(B_DIM * 4096) / 256, 256>>>();
    hist_pass<<<dim3(256, B_DIM), 256>>>(0x00000000u, 20, 0xFFFu);
    find_bin<<<B_DIM, 256>>>(20, 0);
    hist_pass<<<dim3(256, B_DIM), 256>>>(0xFFF00000u, 8, 0xFFFu);
    find_bin<<<B_DIM, 256>>>(8, 0);
    hist_pass<<<dim3(256, B_DIM), 256>>>(0xFFFFFF00u, 0, 0xFFu);
    find_bin<<<B_DIM, 256>>>(0, 1);
    mask_kernel<<<(B_DIM * H_DIM) / 256, 256>>>();

    // merged per-batch up/mod weights + bias (fp16)
    merge_kernel<<<B_DIM * H_DIM, 256>>>(up_w, modw, up_b, modb);

    // H = silu(X @ Wu^T + Bu)           -> half (per-batch weights)
    gemm_h<2><<<gH, 256, GEMM_SMEM>>>(Xh, Wu, Bu, Rh, D_DIM, H_DIM);
    // out = H @ Wd^T + down_b           -> float
    gemm_h<1><<<gD, 256, GEMM_SMEM>>>(Rh, Wd, dwb, out, H_DIM, D_DIM);
}

// round 15
// speedup vs baseline: 8.0417x; 1.3184x over previous
#include <cuda_runtime.h>
#include <cuda_fp16.h>
#include <cstdint>
#include <math.h>

// Problem dims (fixed)
#define B_DIM 8
#define S_DIM 1024
#define D_DIM 1024
#define H_DIM 4096
#define BS_DIM (B_DIM * S_DIM)            // 8192
#define SH_DIM (S_DIM * H_DIM)            // 4194304 per batch
#define KSEL   (1024u * 1024u)            // TOP_K * S = 2^20

// ---------------- scratch (device globals) ---------------------------------
__device__ __align__(1024) __half g_Xh[(size_t)BS_DIM * D_DIM];
__device__ __align__(1024) __half g_W1[(size_t)H_DIM * D_DIM];
__device__ __align__(1024) __half g_W2[(size_t)H_DIM * H_DIM];
__device__ __align__(1024) __half g_Wd[(size_t)D_DIM * H_DIM];
__device__ __align__(1024) __half g_Wup[(size_t)H_DIM * D_DIM];
__device__ __align__(1024) __half g_Wmd[(size_t)H_DIM * D_DIM];
__device__ __align__(1024) __half g_Rh[(size_t)BS_DIM * H_DIM];  // relu R / silu H
__device__ __align__(1024) float  g_Sc[(size_t)BS_DIM * H_DIM];  // scores f32
__device__ float g_Bu[B_DIM * H_DIM];
__device__ unsigned g_Mu[B_DIM * H_DIM];         // colmax as monotonic keys
__device__ unsigned g_hist[B_DIM * 4096];
__device__ unsigned g_prefix[B_DIM];
__device__ unsigned g_need[B_DIM];
__device__ unsigned g_keyvk[B_DIM];
__device__ unsigned char g_mask[B_DIM * H_DIM];

// ---------------- helpers ---------------------------------------------------
__device__ __forceinline__ unsigned fkey(float f) {
    unsigned u = __float_as_uint(f);
    return u ^ ((unsigned)((int)u >> 31) | 0x80000000u);
}
__device__ __forceinline__ uint32_t smem_u32(const void* p) {
    uint32_t a;
    asm("{ .reg .u64 t; cvta.to.shared.u64 t, %1; cvt.u32.u64 %0, t; }"
        : "=r"(a) : "l"(p));
    return a;
}
__device__ __forceinline__ void cp16(uint32_t dst, const void* src) {
    asm volatile("cp.async.cg.shared.global [%0], [%1], 16;"
                 :: "r"(dst), "l"(src));
}
#define CP_COMMIT() asm volatile("cp.async.commit_group;" ::: "memory")
#define CP_WAIT2()  asm volatile("cp.async.wait_group 2;" ::: "memory")
#define CP_WAIT0()  asm volatile("cp.async.wait_group 0;" ::: "memory")

__device__ __forceinline__ void ldsm4(uint32_t& r0, uint32_t& r1,
                                      uint32_t& r2, uint32_t& r3, uint32_t addr) {
    asm volatile("ldmatrix.sync.aligned.m8n8.x4.shared.b16 {%0,%1,%2,%3}, [%4];"
        : "=r"(r0), "=r"(r1), "=r"(r2), "=r"(r3) : "r"(addr));
}
__device__ __forceinline__ void mma_f16(float* c, const uint32_t* a,
                                        const uint32_t* b) {
    asm volatile(
        "mma.sync.aligned.m16n8k16.row.col.f32.f16.f16.f32 "
        "{%0,%1,%2,%3}, {%4,%5,%6,%7}, {%8,%9}, {%0,%1,%2,%3};"
        : "+f"(c[0]), "+f"(c[1]), "+f"(c[2]), "+f"(c[3])
        : "r"(a[0]), "r"(a[1]), "r"(a[2]), "r"(a[3]), "r"(b[0]), "r"(b[1]));
}

// ---------------- fp16 mma GEMM: C[M,N] = A[M,K] @ Bw[rows,K]^T -------------
// tile 128x128, BK=64 halfs (128B rows), 3-stage cp.async, 8 warps (32x64)
// fragment loads via ldmatrix.x4 (6 LDSM per warp-kstep instead of 24 LDS)
// MODE 0: +bias, relu,  half out                    (gate L1 -> R)
// MODE 1: +bias,        float out                   (down proj)
// MODE 2: per-row mask-selected B (up/mod), silu, half out
// MODE 3: +bias, float out + fused level-1 histogram + column-max (scores)
#define STG_A 16384
#define STG   32768
#define NSTG  3
#define GEMM_SMEM (NSTG * STG)

template <int MODE>
__global__ void __launch_bounds__(256, 2) gemm_h(
    const __half* __restrict__ A, const __half* __restrict__ Bw,
    const __half* __restrict__ Bw2, const float* __restrict__ bias,
    void* __restrict__ Cv, int K, int ldc)
{
    extern __shared__ char smraw[];
    const int tid = threadIdx.x;
    const int m0 = blockIdx.x * 128;
    const int n0 = blockIdx.y * 128;
    const int batch = m0 >> 10;
    const int boff = (MODE == 2) ? batch * H_DIM : 0;
    const uint32_t sbase = smem_u32(smraw);

    // ---- cp.async geometry: thread -> (row = tid/8 + 32*jj, 16B chunk = tid%8)
    const int lrow = tid >> 3;
    const int lc   = tid & 7;
    const uint32_t dstoff = (uint32_t)lrow * 128u
                          + (uint32_t)((lc ^ (lrow & 7)) * 16);
    const char* srcA = (const char*)(A + (size_t)(m0 + lrow) * K) + lc * 16;
    const size_t rowstep = (size_t)K * 64;     // 32 rows * K halfs * 2B
    const char* srcB[4];
    #pragma unroll
    for (int jj = 0; jj < 4; jj++) {
        int h = n0 + lrow + 32 * jj;
        const __half* base = Bw;
        if (MODE == 2 && g_mask[batch * H_DIM + h]) base = Bw2;
        srcB[jj] = (const char*)(base + (size_t)h * K) + lc * 16;
    }

    const int NK = K >> 6;                     // BK = 64 halfs

    auto issue = [&](int t) {
        uint32_t sa = sbase + (uint32_t)(t % NSTG) * STG;
        const char* pa = srcA + (size_t)t * 128;
        #pragma unroll
        for (int jj = 0; jj < 4; jj++)
            cp16(sa + jj * 4096 + dstoff, pa + jj * rowstep);
        #pragma unroll
        for (int jj = 0; jj < 4; jj++)
            cp16(sa + STG_A + jj * 4096 + dstoff, srcB[jj] + (size_t)t * 128);
        CP_COMMIT();
    };

    // ---- compute geometry (warp 32x64 tile, 2x8 m16n8k16 frags)
    const int w    = tid >> 5;
    const int lane = tid & 31;
    const int q    = lane >> 2;         // lane/4
    const int p    = lane & 3;          // lane%4
    const int wm0  = (w & 3) * 32;
    const int wn0  = (w >> 2) * 64;
    // ldmatrix per-lane addressing
    const int j8 = lane >> 3, r8 = lane & 7;
    const int rA  = wm0 + ((j8 & 1) << 3) + r8;     // A row, frag i=0
    const int cbA = j8 >> 1;                        // k-half select
    const int swA = rA & 7;
    const int rB  = wn0 + ((j8 >> 1) << 3) + r8;    // B row, frag pair jj=0
    const int cbB = j8 & 1;
    const int swB = rB & 7;
    const uint32_t baseA = (uint32_t)rA * 128u;
    const uint32_t baseB = (uint32_t)rB * 128u + STG_A;

    float acc[2][8][4];
    #pragma unroll
    for (int i = 0; i < 2; i++)
        #pragma unroll
        for (int j = 0; j < 8; j++)
            #pragma unroll
            for (int r = 0; r < 4; r++) acc[i][j][r] = 0.f;

    issue(0); issue(1);

    for (int kc = 0; kc < NK; kc++) {
        if (kc + 2 < NK) { issue(kc + 2); CP_WAIT2(); }
        else             { CP_WAIT0(); }
        __syncthreads();

        uint32_t st = sbase + (uint32_t)(kc % NSTG) * STG;
        #pragma unroll
        for (int ks = 0; ks < 4; ks++) {       // 4 x k16 per 64-half chunk
            uint32_t tA = (uint32_t)(((2 * ks + cbA) ^ swA) * 16);
            uint32_t tB = (uint32_t)(((2 * ks + cbB) ^ swB) * 16);
            uint32_t a[2][4], b[8][2];
            ldsm4(a[0][0], a[0][1], a[0][2], a[0][3], st + baseA + tA);
            ldsm4(a[1][0], a[1][1], a[1][2], a[1][3], st + baseA + 2048 + tA);
            #pragma unroll
            for (int jj = 0; jj < 4; jj++)
                ldsm4(b[2*jj][0], b[2*jj][1], b[2*jj+1][0], b[2*jj+1][1],
                      st + baseB + (uint32_t)jj * 2048 + tB);
            #pragma unroll
            for (int i = 0; i < 2; i++)
                #pragma unroll
                for (int j = 0; j < 8; j++)
                    mma_f16(acc[i][j], a[i], b[j]);
        }
        __syncthreads();
    }

    // ---- epilogue
    unsigned* uhist = (unsigned*)smraw;
    if (MODE == 3) {
        __syncthreads();
        #pragma unroll
        for (int t = 0; t < 16; t++) uhist[tid + t * 256] = 0;
        __syncthreads();
    }

    unsigned cmax[16];
    if (MODE == 3) {
        #pragma unroll
        for (int t = 0; t < 16; t++) cmax[t] = 0;
    }

    #pragma unroll
    for (int i = 0; i < 2; i++) {
        int mr = m0 + wm0 + i * 16 + q;
        #pragma unroll
        for (int j = 0; j < 8; j++) {
            int nc = n0 + wn0 + j * 8 + p * 2;
            float2 bb = *(const float2*)(bias + boff + nc);
            float v0 = acc[i][j][0] + bb.x;
            float v1 = acc[i][j][1] + bb.y;
            float v2 = acc[i][j][2] + bb.x;
            float v3 = acc[i][j][3] + bb.y;
            if (MODE == 0) {
                v0 = fmaxf(v0, 0.f); v1 = fmaxf(v1, 0.f);
                v2 = fmaxf(v2, 0.f); v3 = fmaxf(v3, 0.f);
                __half* Ch = (__half*)Cv;
                *(__half2*)(Ch + (size_t)mr * ldc + nc) = __floats2half2_rn(v0, v1);
                *(__half2*)(Ch + (size_t)(mr + 8) * ldc + nc) = __floats2half2_rn(v2, v3);
            } else if (MODE == 2) {
                v0 = v0 / (1.f + expf(-v0));
                v1 = v1 / (1.f + expf(-v1));
                v2 = v2 / (1.f + expf(-v2));
                v3 = v3 / (1.f + expf(-v3));
                __half* Ch = (__half*)Cv;
                *(__half2*)(Ch + (size_t)mr * ldc + nc) = __floats2half2_rn(v0, v1);
                *(__half2*)(Ch + (size_t)(mr + 8) * ldc + nc) = __floats2half2_rn(v2, v3);
            } else {
                float* Cf = (float*)Cv;
                *(float2*)(Cf + (size_t)mr * ldc + nc) = make_float2(v0, v1);
                *(float2*)(Cf + (size_t)(mr + 8) * ldc + nc) = make_float2(v2, v3);
                if (MODE == 3) {
                    unsigned k0 = fkey(v0), k1 = fkey(v1);
                    unsigned k2 = fkey(v2), k3 = fkey(v3);
                    atomicAdd(&uhist[k0 >> 20], 1u);
                    atomicAdd(&uhist[k1 >> 20], 1u);
                    atomicAdd(&uhist[k2 >> 20], 1u);
                    atomicAdd(&uhist[k3 >> 20], 1u);
                    unsigned a02 = k0 > k2 ? k0 : k2;
                    unsigned a13 = k1 > k3 ? k1 : k3;
                    if (a02 > cmax[2*j])     cmax[2*j]     = a02;
                    if (a13 > cmax[2*j + 1]) cmax[2*j + 1] = a13;
                }
            }
        }
    }

    if (MODE == 3) {
        // column-max: reduce over q (lanes differing in bits 2..4), atomic per col
        #pragma unroll
        for (int t = 0; t < 16; t++) {
            unsigned v = cmax[t];
            v = max(v, __shfl_xor_sync(0xFFFFFFFFu, v, 4));
            v = max(v, __shfl_xor_sync(0xFFFFFFFFu, v, 8));
            v = max(v, __shfl_xor_sync(0xFFFFFFFFu, v, 16));
            cmax[t] = v;
        }
        if (lane < 4) {
            #pragma unroll
            for (int j = 0; j < 8; j++) {
                int nc = n0 + wn0 + j * 8 + p * 2;
                atomicMax(&g_Mu[batch * H_DIM + nc],     cmax[2*j]);
                atomicMax(&g_Mu[batch * H_DIM + nc + 1], cmax[2*j + 1]);
            }
        }
        __syncthreads();
        for (int i = tid; i < 4096; i += 256)
            if (uhist[i]) atomicAdd(&g_hist[batch * 4096 + i], uhist[i]);
    }
}

// ---------------- aux kernels ----------------------------------------------
__global__ void h_copy(const float* __restrict__ src, __half* __restrict__ dst,
                       int n4) {
    int i = blockIdx.x * blockDim.x + threadIdx.x;
    if (i < n4) {
        float4 v = ((const float4*)src)[i];
        __half2* d2 = (__half2*)(dst + (size_t)i * 4);
        d2[0] = __floats2half2_rn(v.x, v.y);
        d2[1] = __floats2half2_rn(v.z, v.w);
    }
}

__global__ void init_sel() {
    int i = blockIdx.x * blockDim.x + threadIdx.x;
    if (i < B_DIM * 4096) { g_hist[i] = 0; g_Mu[i] = 0; }   // B*4096 == B*H
    if (i < B_DIM) { g_prefix[i] = 0; g_need[i] = KSEL; }
}

__global__ void hist_pass(unsigned prefmask, int shift, unsigned binmask) {
    int b = blockIdx.y;
    __shared__ unsigned sh[4096];
    for (int i = threadIdx.x; i < 4096; i += blockDim.x) sh[i] = 0;
    __syncthreads();
    unsigned pref = g_prefix[b] & prefmask;
    const float* p = g_Sc + (size_t)b * SH_DIM;
    int stride = gridDim.x * blockDim.x;
    for (int i = blockIdx.x * blockDim.x + threadIdx.x; i < SH_DIM; i += stride) {
        unsigned key = fkey(p[i]);
        if ((key & prefmask) == pref) {
            unsigned bin = (key >> shift) & binmask;
            unsigned am = __activemask();
            unsigned mset = __match_any_sync(am, bin);
            int leader = __ffs(mset) - 1;
            if ((threadIdx.x & 31) == leader)
                atomicAdd(&sh[bin], (unsigned)__popc(mset));
        }
    }
    __syncthreads();
    for (int i = threadIdx.x; i < 4096; i += blockDim.x)
        if (sh[i]) atomicAdd(&g_hist[b * 4096 + i], sh[i]);
}

__global__ void find_bin(int shift, int final) {
    int b = blockIdx.x;
    __shared__ unsigned sh[4096];
    for (int i = threadIdx.x; i < 4096; i += blockDim.x) {
        sh[i] = g_hist[b * 4096 + i];
        g_hist[b * 4096 + i] = 0;
    }
    __syncthreads();
    if (threadIdx.x == 0) {
        unsigned nd = g_need[b], cum = 0;
        int bin = 4095;
        for (; bin >= 0; --bin) {
            unsigned c = sh[bin];
            if (cum + c >= nd) break;
            cum += c;
        }
        g_need[b] = nd - cum;
        g_prefix[b] |= ((unsigned)bin) << shift;
        if (final) g_keyvk[b] = g_prefix[b];
    }
}

__global__ void mask_bias_kernel(const float* __restrict__ upb,
                                 const float* __restrict__ modb) {
    int i = blockIdx.x * blockDim.x + threadIdx.x;
    int b = i / H_DIM;
    int h = i & (H_DIM - 1);
    bool m = g_Mu[i] >= g_keyvk[b];
    g_mask[i] = m ? 1 : 0;
    g_Bu[i] = m ? modb[h] : upb[h];
}

// ---------------- launch ----------------------------------------------------
extern "C" void kernel_launch(void* const* d_in, const int* in_sizes, int n_in,
                              void* d_out, int out_size)
{
    const float* inputs = (const float*)d_in[0];
    const float* up_w   = (const float*)d_in[1];
    const float* up_b   = (const float*)d_in[2];
    const float* g1w    = (const float*)d_in[3];
    const float* g1b    = (const float*)d_in[4];
    const float* g2w    = (const float*)d_in[5];
    const float* g2b    = (const float*)d_in[6];
    const float* modw   = (const float*)d_in[7];
    const float* modb   = (const float*)d_in[8];
    const float* dww    = (const float*)d_in[9];
    const float* dwb    = (const float*)d_in[10];
    float* out = (float*)d_out;

    __half *Xh, *W1, *W2, *Wd, *Wup, *Wmd, *Rh;
    float *Sc, *Bu;
    cudaGetSymbolAddress((void**)&Xh,  g_Xh);
    cudaGetSymbolAddress((void**)&W1,  g_W1);
    cudaGetSymbolAddress((void**)&W2,  g_W2);
    cudaGetSymbolAddress((void**)&Wd,  g_Wd);
    cudaGetSymbolAddress((void**)&Wup, g_Wup);
    cudaGetSymbolAddress((void**)&Wmd, g_Wmd);
    cudaGetSymbolAddress((void**)&Rh,  g_Rh);
    cudaGetSymbolAddress((void**)&Sc,  g_Sc);
    cudaGetSymbolAddress((void**)&Bu,  g_Bu);

    cudaFuncSetAttribute(gemm_h<0>, cudaFuncAttributeMaxDynamicSharedMemorySize, GEMM_SMEM);
    cudaFuncSetAttribute(gemm_h<1>, cudaFuncAttributeMaxDynamicSharedMemorySize, GEMM_SMEM);
    cudaFuncSetAttribute(gemm_h<2>, cudaFuncAttributeMaxDynamicSharedMemorySize, GEMM_SMEM);
    cudaFuncSetAttribute(gemm_h<3>, cudaFuncAttributeMaxDynamicSharedMemorySize, GEMM_SMEM);

    // fp16 operand conversion (RN, unbiased; same 10-bit mantissa as tf32)
    h_copy<<<(BS_DIM * D_DIM / 4 + 255) / 256, 256>>>(inputs, Xh, BS_DIM * D_DIM / 4);
    h_copy<<<(H_DIM * D_DIM / 4 + 255) / 256, 256>>>(g1w, W1, H_DIM * D_DIM / 4);
    h_copy<<<(H_DIM * H_DIM / 4 + 255) / 256, 256>>>(g2w, W2, H_DIM * H_DIM / 4);
    h_copy<<<(D_DIM * H_DIM / 4 + 255) / 256, 256>>>(dww, Wd, D_DIM * H_DIM / 4);
    h_copy<<<(H_DIM * D_DIM / 4 + 255) / 256, 256>>>(up_w, Wup, H_DIM * D_DIM / 4);
    h_copy<<<(H_DIM * D_DIM / 4 + 255) / 256, 256>>>(modw, Wmd, H_DIM * D_DIM / 4);

    init_sel<<<(B_DIM * 4096) / 256, 256>>>();

    dim3 gH(BS_DIM / 128, H_DIM / 128);     // 64 x 32
    dim3 gD(BS_DIM / 128, D_DIM / 128);     // 64 x 8

    // gate L1: R = relu(X @ W1^T + b1)  -> half
    gemm_h<0><<<gH, 256, GEMM_SMEM>>>(Xh, W1, nullptr, g1b, Rh, D_DIM, H_DIM);
    // gate L2: Sc = R @ W2^T + b2 -> float, + fused level-1 hist + colmax
    gemm_h<3><<<gH, 256, GEMM_SMEM>>>(Rh, W2, nullptr, g2b, Sc, H_DIM, H_DIM);

    // radix-select refinement (levels 2,3 scan Sc; level 1 came from epilogue)
    find_bin<<<B_DIM, 256>>>(20, 0);
    hist_pass<<<dim3(256, B_DIM), 256>>>(0xFFF00000u, 8, 0xFFFu);
    find_bin<<<B_DIM, 256>>>(8, 0);
    hist_pass<<<dim3(256, B_DIM), 256>>>(0xFFFFFF00u, 0, 0xFFu);
    find_bin<<<B_DIM, 256>>>(0, 1);
    mask_bias_kernel<<<(B_DIM * H_DIM) / 256, 256>>>(up_b, modb);

    // H = silu(X @ (mask? mod_w : up_w)^T + Bu) -> half (per-row select)
    gemm_h<2><<<gH, 256, GEMM_SMEM>>>(Xh, Wup, Wmd, Bu, Rh, D_DIM, H_DIM);
    // out = H @ Wd^T + down_b -> float
    gemm_h<1><<<gD, 256, GEMM_SMEM>>>(Rh, Wd, nullptr, dwb, out, H_DIM, D_DIM);
}

// round 16
// speedup vs baseline: 8.2505x; 1.0260x over previous
#include <cuda_runtime.h>
#include <cuda_fp16.h>
#include <cstdint>
#include <math.h>

// Problem dims (fixed)
#define B_DIM 8
#define S_DIM 1024
#define D_DIM 1024
#define H_DIM 4096
#define BS_DIM (B_DIM * S_DIM)            // 8192
#define SH_DIM (S_DIM * H_DIM)            // 4194304 per batch
#define KSEL   (1024u * 1024u)            // TOP_K * S = 2^20

// ---------------- scratch (device globals) ---------------------------------
__device__ __align__(1024) __half g_Xh[(size_t)BS_DIM * D_DIM];
__device__ __align__(1024) __half g_W1[(size_t)H_DIM * D_DIM];
__device__ __align__(1024) __half g_W2[(size_t)H_DIM * H_DIM];
__device__ __align__(1024) __half g_Wd[(size_t)D_DIM * H_DIM];
__device__ __align__(1024) __half g_Wup[(size_t)H_DIM * D_DIM];
__device__ __align__(1024) __half g_Wmd[(size_t)H_DIM * D_DIM];
__device__ __align__(1024) __half g_Rh[(size_t)BS_DIM * H_DIM];  // relu R / silu H
__device__ __align__(1024) float  g_Sc[(size_t)BS_DIM * H_DIM];  // scores f32
__device__ float g_Bu[B_DIM * H_DIM];
__device__ unsigned g_Mu[B_DIM * H_DIM];         // colmax as monotonic keys
__device__ unsigned g_hist[B_DIM * 4096];
__device__ unsigned g_prefix[B_DIM];
__device__ unsigned g_need[B_DIM];
__device__ unsigned g_keyvk[B_DIM];
__device__ unsigned char g_mask[B_DIM * H_DIM];

// ---------------- helpers ---------------------------------------------------
__device__ __forceinline__ unsigned fkey(float f) {
    unsigned u = __float_as_uint(f);
    return u ^ ((unsigned)((int)u >> 31) | 0x80000000u);
}
__device__ __forceinline__ uint32_t smem_u32(const void* p) {
    uint32_t a;
    asm("{ .reg .u64 t; cvta.to.shared.u64 t, %1; cvt.u32.u64 %0, t; }"
        : "=r"(a) : "l"(p));
    return a;
}
__device__ __forceinline__ void cp16(uint32_t dst, const void* src) {
    asm volatile("cp.async.cg.shared.global [%0], [%1], 16;"
                 :: "r"(dst), "l"(src));
}
#define CP_COMMIT() asm volatile("cp.async.commit_group;" ::: "memory")
#define CP_WAIT3()  asm volatile("cp.async.wait_group 3;" ::: "memory")
#define CP_WAIT2()  asm volatile("cp.async.wait_group 2;" ::: "memory")
#define CP_WAIT0()  asm volatile("cp.async.wait_group 0;" ::: "memory")

__device__ __forceinline__ void ldsm4(uint32_t& r0, uint32_t& r1,
                                      uint32_t& r2, uint32_t& r3, uint32_t addr) {
    asm volatile("ldmatrix.sync.aligned.m8n8.x4.shared.b16 {%0,%1,%2,%3}, [%4];"
        : "=r"(r0), "=r"(r1), "=r"(r2), "=r"(r3) : "r"(addr));
}
__device__ __forceinline__ void mma_f16(float* c, const uint32_t* a,
                                        const uint32_t* b) {
    asm volatile(
        "mma.sync.aligned.m16n8k16.row.col.f32.f16.f16.f32 "
        "{%0,%1,%2,%3}, {%4,%5,%6,%7}, {%8,%9}, {%0,%1,%2,%3};"
        : "+f"(c[0]), "+f"(c[1]), "+f"(c[2]), "+f"(c[3])
        : "r"(a[0]), "r"(a[1]), "r"(a[2]), "r"(a[3]), "r"(b[0]), "r"(b[1]));
}

// ============ WIDE engine: 128(M) x 256(N) tile, 256 thr, warp 64x64 ========
// 4-stage cp.async (192KB smem, 1 CTA/SM). BK=64 halfs (128B rows).
// MODE 0: +bias, relu, half out
// MODE 2: per-row mask-selected B (up/mod), silu, half out
// MODE 3: +bias, float out + fused level-1 histogram + column-max
#define WSTG_A 16384
#define WSTG   49152          // A 16KB + B 32KB
#define WNSTG  4
#define WSMEM  (WNSTG * WSTG) // 196608

template <int MODE>
__global__ void __launch_bounds__(256, 1) gemm_w(
    const __half* __restrict__ A, const __half* __restrict__ Bw,
    const __half* __restrict__ Bw2, const float* __restrict__ bias,
    void* __restrict__ Cv, int K, int ldc)
{
    extern __shared__ char smraw[];
    const int tid = threadIdx.x;
    const int m0 = blockIdx.x * 128;
    const int n0 = blockIdx.y * 256;
    const int batch = m0 >> 10;
    const int boff = (MODE == 2) ? batch * H_DIM : 0;
    const uint32_t sbase = smem_u32(smraw);

    // ---- loader: row = tid/8 + 32*jj, 16B chunk = tid%8 (proven pattern)
    const int lrow = tid >> 3;
    const int lc   = tid & 7;
    const uint32_t dstoff = (uint32_t)lrow * 128u
                          + (uint32_t)((lc ^ (lrow & 7)) * 16);
    const char* srcA = (const char*)(A + (size_t)(m0 + lrow) * K) + lc * 16;
    const size_t rowstep = (size_t)K * 64;     // 32 rows * K halfs * 2B
    const char* srcB[8];
    #pragma unroll
    for (int jj = 0; jj < 8; jj++) {
        int h = n0 + lrow + 32 * jj;
        const __half* base = Bw;
        if (MODE == 2 && g_mask[batch * H_DIM + h]) base = Bw2;
        srcB[jj] = (const char*)(base + (size_t)h * K) + lc * 16;
    }

    const int NK = K >> 6;

    auto issue = [&](int t) {
        uint32_t sa = sbase + (uint32_t)(t & (WNSTG - 1)) * WSTG;
        const char* pa = srcA + (size_t)t * 128;
        #pragma unroll
        for (int jj = 0; jj < 4; jj++)
            cp16(sa + jj * 4096 + dstoff, pa + jj * rowstep);
        #pragma unroll
        for (int jj = 0; jj < 8; jj++)
            cp16(sa + WSTG_A + jj * 4096 + dstoff, srcB[jj] + (size_t)t * 128);
        CP_COMMIT();
    };

    // ---- compute geometry: 8 warps as 2(M) x 4(N), each 64x64
    const int w    = tid >> 5;
    const int lane = tid & 31;
    const int q    = lane >> 2;
    const int p    = lane & 3;
    const int wm   = (w & 1) * 64;
    const int wn   = (w >> 1) * 64;
    const int j8 = lane >> 3, r8 = lane & 7;
    const int rA  = wm + ((j8 & 1) << 3) + r8;
    const int cbA = j8 >> 1;
    const int swA = rA & 7;
    const int rB  = wn + ((j8 >> 1) << 3) + r8;
    const int cbB = j8 & 1;
    const int swB = rB & 7;
    const uint32_t baseA = (uint32_t)rA * 128u;
    const uint32_t baseB = (uint32_t)rB * 128u + WSTG_A;

    float acc[4][8][4];
    #pragma unroll
    for (int i = 0; i < 4; i++)
        #pragma unroll
        for (int j = 0; j < 8; j++)
            #pragma unroll
            for (int r = 0; r < 4; r++) acc[i][j][r] = 0.f;

    issue(0); issue(1); issue(2);

    for (int kc = 0; kc < NK; kc++) {
        if (kc + 3 < NK) { issue(kc + 3); CP_WAIT3(); }
        else             { CP_WAIT0(); }
        __syncthreads();

        uint32_t st = sbase + (uint32_t)(kc & (WNSTG - 1)) * WSTG;
        #pragma unroll
        for (int ks = 0; ks < 4; ks++) {
            uint32_t tA = (uint32_t)(((2 * ks + cbA) ^ swA) * 16);
            uint32_t tB = (uint32_t)(((2 * ks + cbB) ^ swB) * 16);
            uint32_t a[4][4], b[8][2];
            #pragma unroll
            for (int i = 0; i < 4; i++)
                ldsm4(a[i][0], a[i][1], a[i][2], a[i][3],
                      st + baseA + (uint32_t)i * 2048 + tA);
            #pragma unroll
            for (int jj = 0; jj < 4; jj++)
                ldsm4(b[2*jj][0], b[2*jj][1], b[2*jj+1][0], b[2*jj+1][1],
                      st + baseB + (uint32_t)jj * 2048 + tB);
            #pragma unroll
            for (int i = 0; i < 4; i++)
                #pragma unroll
                for (int j = 0; j < 8; j++)
                    mma_f16(acc[i][j], a[i], b[j]);
        }
        __syncthreads();
    }

    // ---- epilogue
    unsigned* uhist = (unsigned*)smraw;
    if (MODE == 3) {
        __syncthreads();
        #pragma unroll
        for (int t = 0; t < 16; t++) uhist[tid + t * 256] = 0;
        __syncthreads();
    }

    unsigned cmax[16];
    if (MODE == 3) {
        #pragma unroll
        for (int t = 0; t < 16; t++) cmax[t] = 0;
    }

    #pragma unroll
    for (int i = 0; i < 4; i++) {
        int mr = m0 + wm + i * 16 + q;
        #pragma unroll
        for (int j = 0; j < 8; j++) {
            int nc = n0 + wn + j * 8 + p * 2;
            float2 bb = *(const float2*)(bias + boff + nc);
            float v0 = acc[i][j][0] + bb.x;
            float v1 = acc[i][j][1] + bb.y;
            float v2 = acc[i][j][2] + bb.x;
            float v3 = acc[i][j][3] + bb.y;
            if (MODE == 0) {
                v0 = fmaxf(v0, 0.f); v1 = fmaxf(v1, 0.f);
                v2 = fmaxf(v2, 0.f); v3 = fmaxf(v3, 0.f);
                __half* Ch = (__half*)Cv;
                *(__half2*)(Ch + (size_t)mr * ldc + nc) = __floats2half2_rn(v0, v1);
                *(__half2*)(Ch + (size_t)(mr + 8) * ldc + nc) = __floats2half2_rn(v2, v3);
            } else if (MODE == 2) {
                v0 = v0 / (1.f + expf(-v0));
                v1 = v1 / (1.f + expf(-v1));
                v2 = v2 / (1.f + expf(-v2));
                v3 = v3 / (1.f + expf(-v3));
                __half* Ch = (__half*)Cv;
                *(__half2*)(Ch + (size_t)mr * ldc + nc) = __floats2half2_rn(v0, v1);
                *(__half2*)(Ch + (size_t)(mr + 8) * ldc + nc) = __floats2half2_rn(v2, v3);
            } else {
                float* Cf = (float*)Cv;
                *(float2*)(Cf + (size_t)mr * ldc + nc) = make_float2(v0, v1);
                *(float2*)(Cf + (size_t)(mr + 8) * ldc + nc) = make_float2(v2, v3);
                if (MODE == 3) {
                    unsigned k0 = fkey(v0), k1 = fkey(v1);
                    unsigned k2 = fkey(v2), k3 = fkey(v3);
                    atomicAdd(&uhist[k0 >> 20], 1u);
                    atomicAdd(&uhist[k1 >> 20], 1u);
                    atomicAdd(&uhist[k2 >> 20], 1u);
                    atomicAdd(&uhist[k3 >> 20], 1u);
                    unsigned a02 = k0 > k2 ? k0 : k2;
                    unsigned a13 = k1 > k3 ? k1 : k3;
                    if (a02 > cmax[2*j])     cmax[2*j]     = a02;
                    if (a13 > cmax[2*j + 1]) cmax[2*j + 1] = a13;
                }
            }
        }
    }

    if (MODE == 3) {
        #pragma unroll
        for (int t = 0; t < 16; t++) {
            unsigned v = cmax[t];
            v = max(v, __shfl_xor_sync(0xFFFFFFFFu, v, 4));
            v = max(v, __shfl_xor_sync(0xFFFFFFFFu, v, 8));
            v = max(v, __shfl_xor_sync(0xFFFFFFFFu, v, 16));
            cmax[t] = v;
        }
        if (lane < 4) {
            #pragma unroll
            for (int j = 0; j < 8; j++) {
                int nc = n0 + wn + j * 8 + p * 2;
                atomicMax(&g_Mu[batch * H_DIM + nc],     cmax[2*j]);
                atomicMax(&g_Mu[batch * H_DIM + nc + 1], cmax[2*j + 1]);
            }
        }
        __syncthreads();
        for (int i = tid; i < 4096; i += 256)
            if (uhist[i]) atomicAdd(&g_hist[batch * 4096 + i], uhist[i]);
    }
}

// ============ narrow engine (R15, kept for the N=1024 down-proj) ============
#define STG_A 16384
#define STG   32768
#define NSTG  3
#define GEMM_SMEM (NSTG * STG)

__global__ void __launch_bounds__(256, 2) gemm_h1(
    const __half* __restrict__ A, const __half* __restrict__ Bw,
    const float* __restrict__ bias, float* __restrict__ C, int K, int ldc)
{
    extern __shared__ char smraw[];
    const int tid = threadIdx.x;
    const int m0 = blockIdx.x * 128;
    const int n0 = blockIdx.y * 128;
    const uint32_t sbase = smem_u32(smraw);

    const int lrow = tid >> 3;
    const int lc   = tid & 7;
    const uint32_t dstoff = (uint32_t)lrow * 128u
                          + (uint32_t)((lc ^ (lrow & 7)) * 16);
    const char* srcA = (const char*)(A  + (size_t)(m0 + lrow) * K) + lc * 16;
    const char* srcB = (const char*)(Bw + (size_t)(n0 + lrow) * K) + lc * 16;
    const size_t rowstep = (size_t)K * 64;

    const int NK = K >> 6;

    auto issue = [&](int t) {
        uint32_t sa = sbase + (uint32_t)(t % NSTG) * STG;
        const char* pa = srcA + (size_t)t * 128;
        const char* pb = srcB + (size_t)t * 128;
        #pragma unroll
        for (int jj = 0; jj < 4; jj++)
            cp16(sa + jj * 4096 + dstoff, pa + jj * rowstep);
        #pragma unroll
        for (int jj = 0; jj < 4; jj++)
            cp16(sa + STG_A + jj * 4096 + dstoff, pb + jj * rowstep);
        CP_COMMIT();
    };

    const int w    = tid >> 5;
    const int lane = tid & 31;
    const int q    = lane >> 2;
    const int p    = lane & 3;
    const int wm0  = (w & 3) * 32;
    const int wn0  = (w >> 2) * 64;
    const int j8 = lane >> 3, r8 = lane & 7;
    const int rA  = wm0 + ((j8 & 1) << 3) + r8;
    const int cbA = j8 >> 1;
    const int swA = rA & 7;
    const int rB  = wn0 + ((j8 >> 1) << 3) + r8;
    const int cbB = j8 & 1;
    const int swB = rB & 7;
    const uint32_t baseA = (uint32_t)rA * 128u;
    const uint32_t baseB = (uint32_t)rB * 128u + STG_A;

    float acc[2][8][4];
    #pragma unroll
    for (int i = 0; i < 2; i++)
        #pragma unroll
        for (int j = 0; j < 8; j++)
            #pragma unroll
            for (int r = 0; r < 4; r++) acc[i][j][r] = 0.f;

    issue(0); issue(1);

    for (int kc = 0; kc < NK; kc++) {
        if (kc + 2 < NK) { issue(kc + 2); CP_WAIT2(); }
        else             { CP_WAIT0(); }
        __syncthreads();

        uint32_t st = sbase + (uint32_t)(kc % NSTG) * STG;
        #pragma unroll
        for (int ks = 0; ks < 4; ks++) {
            uint32_t tA = (uint32_t)(((2 * ks + cbA) ^ swA) * 16);
            uint32_t tB = (uint32_t)(((2 * ks + cbB) ^ swB) * 16);
            uint32_t a[2][4], b[8][2];
            ldsm4(a[0][0], a[0][1], a[0][2], a[0][3], st + baseA + tA);
            ldsm4(a[1][0], a[1][1], a[1][2], a[1][3], st + baseA + 2048 + tA);
            #pragma unroll
            for (int jj = 0; jj < 4; jj++)
                ldsm4(b[2*jj][0], b[2*jj][1], b[2*jj+1][0], b[2*jj+1][1],
                      st + baseB + (uint32_t)jj * 2048 + tB);
            #pragma unroll
            for (int i = 0; i < 2; i++)
                #pragma unroll
                for (int j = 0; j < 8; j++)
                    mma_f16(acc[i][j], a[i], b[j]);
        }
        __syncthreads();
    }

    #pragma unroll
    for (int i = 0; i < 2; i++) {
        int mr = m0 + wm0 + i * 16 + q;
        #pragma unroll
        for (int j = 0; j < 8; j++) {
            int nc = n0 + wn0 + j * 8 + p * 2;
            float2 bb = *(const float2*)(bias + nc);
            *(float2*)(C + (size_t)mr * ldc + nc) =
                make_float2(acc[i][j][0] + bb.x, acc[i][j][1] + bb.y);
            *(float2*)(C + (size_t)(mr + 8) * ldc + nc) =
                make_float2(acc[i][j][2] + bb.x, acc[i][j][3] + bb.y);
        }
    }
}

// ---------------- aux kernels ----------------------------------------------
__global__ void h_copy(const float* __restrict__ src, __half* __restrict__ dst,
                       int n4) {
    int i = blockIdx.x * blockDim.x + threadIdx.x;
    if (i < n4) {
        float4 v = ((const float4*)src)[i];
        __half2* d2 = (__half2*)(dst + (size_t)i * 4);
        d2[0] = __floats2half2_rn(v.x, v.y);
        d2[1] = __floats2half2_rn(v.z, v.w);
    }
}

__global__ void init_sel() {
    int i = blockIdx.x * blockDim.x + threadIdx.x;
    if (i < B_DIM * 4096) { g_hist[i] = 0; g_Mu[i] = 0; }
    if (i < B_DIM) { g_prefix[i] = 0; g_need[i] = KSEL; }
}

__global__ void hist_pass(unsigned prefmask, int shift, unsigned binmask) {
    int b = blockIdx.y;
    __shared__ unsigned sh[4096];
    for (int i = threadIdx.x; i < 4096; i += blockDim.x) sh[i] = 0;
    __syncthreads();
    unsigned pref = g_prefix[b] & prefmask;
    const float* p = g_Sc + (size_t)b * SH_DIM;
    int stride = gridDim.x * blockDim.x;
    for (int i = blockIdx.x * blockDim.x + threadIdx.x; i < SH_DIM; i += stride) {
        unsigned key = fkey(p[i]);
        if ((key & prefmask) == pref) {
            unsigned bin = (key >> shift) & binmask;
            unsigned am = __activemask();
            unsigned mset = __match_any_sync(am, bin);
            int leader = __ffs(mset) - 1;
            if ((threadIdx.x & 31) == leader)
                atomicAdd(&sh[bin], (unsigned)__popc(mset));
        }
    }
    __syncthreads();
    for (int i = threadIdx.x; i < 4096; i += blockDim.x)
        if (sh[i]) atomicAdd(&g_hist[b * 4096 + i], sh[i]);
}

// parallel chunk-sum find_bin: serial part is 256+16 iterations, not 4096
__global__ void find_bin(int shift, int final) {
    int b = blockIdx.x;
    __shared__ unsigned sh[4096];
    __shared__ unsigned csum[256];
    int t = threadIdx.x;
    for (int i = t; i < 4096; i += 256) {
        sh[i] = g_hist[b * 4096 + i];
        g_hist[b * 4096 + i] = 0;
    }
    __syncthreads();
    unsigned s = 0;
    #pragma unroll
    for (int k = 0; k < 16; k++) s += sh[4095 - (t * 16 + k)];
    csum[t] = s;
    __syncthreads();
    if (t == 0) {
        unsigned nd = g_need[b], cum = 0;
        int c = 0;
        for (; c < 256; c++) {
            if (cum + csum[c] >= nd) break;
            cum += csum[c];
        }
        int bin = 4095 - c * 16;
        for (int k = 0; k < 16; k++) {
            unsigned v = sh[bin];
            if (cum + v >= nd) break;
            cum += v; bin--;
        }
        g_need[b] = nd - cum;
        g_prefix[b] |= ((unsigned)bin) << shift;
        if (final) g_keyvk[b] = g_prefix[b];
    }
}

__global__ void mask_bias_kernel(const float* __restrict__ upb,
                                 const float* __restrict__ modb) {
    int i = blockIdx.x * blockDim.x + threadIdx.x;
    int b = i / H_DIM;
    int h = i & (H_DIM - 1);
    bool m = g_Mu[i] >= g_keyvk[b];
    g_mask[i] = m ? 1 : 0;
    g_Bu[i] = m ? modb[h] : upb[h];
}

// ---------------- launch ----------------------------------------------------
extern "C" void kernel_launch(void* const* d_in, const int* in_sizes, int n_in,
                              void* d_out, int out_size)
{
    const float* inputs = (const float*)d_in[0];
    const float* up_w   = (const float*)d_in[1];
    const float* up_b   = (const float*)d_in[2];
    const float* g1w    = (const float*)d_in[3];
    const float* g1b    = (const float*)d_in[4];
    const float* g2w    = (const float*)d_in[5];
    const float* g2b    = (const float*)d_in[6];
    const float* modw   = (const float*)d_in[7];
    const float* modb   = (const float*)d_in[8];
    const float* dww    = (const float*)d_in[9];
    const float* dwb    = (const float*)d_in[10];
    float* out = (float*)d_out;

    __half *Xh, *W1, *W2, *Wd, *Wup, *Wmd, *Rh;
    float *Sc, *Bu;
    cudaGetSymbolAddress((void**)&Xh,  g_Xh);
    cudaGetSymbolAddress((void**)&W1,  g_W1);
    cudaGetSymbolAddress((void**)&W2,  g_W2);
    cudaGetSymbolAddress((void**)&Wd,  g_Wd);
    cudaGetSymbolAddress((void**)&Wup, g_Wup);
    cudaGetSymbolAddress((void**)&Wmd, g_Wmd);
    cudaGetSymbolAddress((void**)&Rh,  g_Rh);
    cudaGetSymbolAddress((void**)&Sc,  g_Sc);
    cudaGetSymbolAddress((void**)&Bu,  g_Bu);

    cudaFuncSetAttribute(gemm_w<0>, cudaFuncAttributeMaxDynamicSharedMemorySize, WSMEM);
    cudaFuncSetAttribute(gemm_w<2>, cudaFuncAttributeMaxDynamicSharedMemorySize, WSMEM);
    cudaFuncSetAttribute(gemm_w<3>, cudaFuncAttributeMaxDynamicSharedMemorySize, WSMEM);
    cudaFuncSetAttribute(gemm_h1,   cudaFuncAttributeMaxDynamicSharedMemorySize, GEMM_SMEM);

    // fp16 operand conversion (RN, unbiased)
    h_copy<<<(BS_DIM * D_DIM / 4 + 255) / 256, 256>>>(inputs, Xh, BS_DIM * D_DIM / 4);
    h_copy<<<(H_DIM * D_DIM / 4 + 255) / 256, 256>>>(g1w, W1, H_DIM * D_DIM / 4);
    h_copy<<<(H_DIM * H_DIM / 4 + 255) / 256, 256>>>(g2w, W2, H_DIM * H_DIM / 4);
    h_copy<<<(D_DIM * H_DIM / 4 + 255) / 256, 256>>>(dww, Wd, D_DIM * H_DIM / 4);
    h_copy<<<(H_DIM * D_DIM / 4 + 255) / 256, 256>>>(up_w, Wup, H_DIM * D_DIM / 4);
    h_copy<<<(H_DIM * D_DIM / 4 + 255) / 256, 256>>>(modw, Wmd, H_DIM * D_DIM / 4);

    init_sel<<<(B_DIM * 4096) / 256, 256>>>();

    dim3 gW(BS_DIM / 128, H_DIM / 256);     // 64 x 16 (wide engine)
    dim3 gD(BS_DIM / 128, D_DIM / 128);     // 64 x 8  (narrow engine)

    // gate L1: R = relu(X @ W1^T + b1)  -> half
    gemm_w<0><<<gW, 256, WSMEM>>>(Xh, W1, nullptr, g1b, Rh, D_DIM, H_DIM);
    // gate L2: Sc = R @ W2^T + b2 -> float, + fused level-1 hist + colmax
    gemm_w<3><<<gW, 256, WSMEM>>>(Rh, W2, nullptr, g2b, Sc, H_DIM, H_DIM);

    // radix-select refinement (levels 2,3 scan Sc; level 1 from epilogue)
    find_bin<<<B_DIM, 256>>>(20, 0);
    hist_pass<<<dim3(256, B_DIM), 256>>>(0xFFF00000u, 8, 0xFFFu);
    find_bin<<<B_DIM, 256>>>(8, 0);
    hist_pass<<<dim3(256, B_DIM), 256>>>(0xFFFFFF00u, 0, 0xFFu);
    find_bin<<<B_DIM, 256>>>(0, 1);
    mask_bias_kernel<<<(B_DIM * H_DIM) / 256, 256>>>(up_b, modb);

    // H = silu(X @ (mask? mod_w : up_w)^T + Bu) -> half (per-row select)
    gemm_w<2><<<gW, 256, WSMEM>>>(Xh, Wup, Wmd, Bu, Rh, D_DIM, H_DIM);
    // out = H @ Wd^T + down_b -> float (narrow engine)
    gemm_h1<<<gD, 256, GEMM_SMEM>>>(Rh, Wd, dwb, out, H_DIM, D_DIM);
}